// round 13
// baseline (speedup 1.0000x reference)
#include <cuda_runtime.h>

// ---------------------------------------------------------------------------
// GAT collapses (uniform per-item node features; per-dst softmax weights sum
// to 1 via self-loops) => whole model = 7-layer MLP on 64 batch rows.
// SINGLE kernel: 32 clusters x 4 CTAs x 512 thr (128 CTAs = full chip).
// Cluster owns 2 rows; each CTA computes 64/256 outputs per big layer;
// results broadcast to peers via st.shared::cluster + barrier.cluster, with
// the next layer's weight LDGs issued between cluster arrive and wait.
// Weights are read RAW (row-major): thread (kq, o) loads a contiguous 128B
// chunk of its row -> same L1/L2 traffic as a packed layout, no pack kernel.
// ---------------------------------------------------------------------------

typedef unsigned long long ULL;
typedef unsigned int U32;

__device__ __forceinline__ void ffma2(ULL& d, ULL a, ULL b) {
    asm("fma.rn.f32x2 %0, %1, %2, %0;" : "+l"(d) : "l"(a), "l"(b));
}
__device__ __forceinline__ void fadd2(ULL& d, ULL a) {
    asm("add.rn.f32x2 %0, %1, %0;" : "+l"(d) : "l"(a));
}
__device__ __forceinline__ float2 unpack2f(ULL v) {
    float2 f; asm("mov.b64 {%0, %1}, %2;" : "=f"(f.x), "=f"(f.y) : "l"(v)); return f;
}
__device__ __forceinline__ U32 smem_u32(const void* p) {
    return (U32)__cvta_generic_to_shared(p);
}
#define CLUSTER_ARRIVE() asm volatile("barrier.cluster.arrive.aligned;" ::: "memory")
#define CLUSTER_WAIT()   asm volatile("barrier.cluster.wait.aligned;"   ::: "memory")

// Contiguous weight fetch: N float4 quads from a raw row pointer.
template<int N>
__device__ __forceinline__ void loadw(longlong2* wr, const float* p) {
    const longlong2* q = (const longlong2*)p;
    #pragma unroll
    for (int i = 0; i < N; i++) wr[i] = q[i];
}

__global__ __launch_bounds__(512, 1) __cluster_dims__(4, 1, 1)
void net_kernel(
    const float* __restrict__ x, const int* __restrict__ cidx,
    const float* __restrict__ W_in, const float* __restrict__ b_in,
    const float* __restrict__ gat_W, const float* __restrict__ gat_b,
    const float* __restrict__ emb,
    const float* __restrict__ W_fuse, const float* __restrict__ b_fuse,
    const float* __restrict__ W_p1, const float* __restrict__ b_p1,
    const float* __restrict__ W_p2, const float* __restrict__ b_p2,
    const float* __restrict__ W_p3, const float* __restrict__ b_p3,
    const float* __restrict__ W_d1, const float* __restrict__ b_d1,
    const float* __restrict__ W_d2, const float* __restrict__ b_d2,
    const float* __restrict__ W_d3, const float* __restrict__ b_d3,
    float* __restrict__ out) {

    __shared__ __align__(16) float  X[2][64];
    __shared__ __align__(16) float  A[2][336];
    __shared__ __align__(16) float  B[2][336];
    __shared__ __align__(16) float2 P[8][64];
    __shared__ __align__(16) float  C[128];

    const int t  = threadIdx.x;
    const int o  = t & 63;      // output within CTA's 64-slice (big layers)
    const int kq = t >> 6;      // K eighth 0..7
    U32 rank; asm("mov.u32 %0, %%cluster_ctarank;" : "=r"(rank));
    const int row0 = (blockIdx.x >> 2) * 2;      // cluster's first global row
    const int ro   = (int)rank * 64 + o;         // this thread's big-layer row
    const int kq2 = t >> 7;                      // tail: K quarter 0..3
    const int o2  = t & 127;                     // tail: 0..63 p2, 64..127 d2
    const int oc0 = t & 255, kh0 = t >> 8;       // L0-local mapping

    longlong2 wr[10];

    // Prefetch L0 weights immediately (raw row chunk).
    loadw<8>(wr, W_in + oc0 * 64 + kh0 * 32);

    // ---- stage inputs ----
    if (t < 32) {
        int r = t >> 4, q = t & 15;
        ((float4*)X[r])[q] = ((const float4*)x)[(row0 + r) * 16 + q];
    } else if (t < 64) {
        int i = t - 32, r = i >> 4, q = i & 15;
        int ci = cidx[row0 + r];
        ((float4*)(B[r] + 256))[q] = ((const float4*)emb)[ci * 16 + q];
    }
    __syncthreads();

    // ===== L0 (CTA-local, all 256 outputs, K=64): X -> A =====
    {
        float2 (*P2)[256] = (float2 (*)[256])&P[0][0];
        const longlong2* a0 = (const longlong2*)X[0] + kh0 * 8;
        const longlong2* a1 = (const longlong2*)X[1] + kh0 * 8;
        ULL p0 = 0ull, q0 = 0ull, p1 = 0ull, q1 = 0ull;
        #pragma unroll
        for (int i = 0; i < 8; i++) {
            longlong2 x0 = a0[i], x1 = a1[i];
            ffma2(p0, (ULL)wr[i].x, (ULL)x0.x);
            ffma2(q0, (ULL)wr[i].y, (ULL)x0.y);
            ffma2(p1, (ULL)wr[i].x, (ULL)x1.x);
            ffma2(q1, (ULL)wr[i].y, (ULL)x1.y);
        }
        fadd2(p0, q0); fadd2(p1, q1);
        float2 f0 = unpack2f(p0), f1 = unpack2f(p1);
        P2[kh0][oc0] = make_float2(f0.x + f0.y, f1.x + f1.y);
        // Prefetch L1 weights while partials settle.
        loadw<8>(wr, gat_W + ro * 256 + kq * 32);
        __syncthreads();
        {
            int rr = t >> 8, oc = t & 255;
            float v = rr ? (P2[0][oc].y + P2[1][oc].y)
                         : (P2[0][oc].x + P2[1][oc].x);
            A[rr][oc] = fmaxf(v + b_in[oc], 0.f);
        }
        __syncthreads();
    }

    // FFMA phase over this thread's K-slice; partials into P.
    #define COMPUTE(KQ4, IN)                                                  \
    {                                                                         \
        const longlong2* a0 = (const longlong2*)IN[0] + kq * (KQ4);           \
        const longlong2* a1 = (const longlong2*)IN[1] + kq * (KQ4);           \
        ULL p0 = 0ull, q0 = 0ull, p1 = 0ull, q1 = 0ull;                       \
        _Pragma("unroll")                                                     \
        for (int i = 0; i < (KQ4); i++) {                                     \
            longlong2 x0 = a0[i], x1 = a1[i];                                 \
            ffma2(p0, (ULL)wr[i].x, (ULL)x0.x);                               \
            ffma2(q0, (ULL)wr[i].y, (ULL)x0.y);                               \
            ffma2(p1, (ULL)wr[i].x, (ULL)x1.x);                               \
            ffma2(q1, (ULL)wr[i].y, (ULL)x1.y);                               \
        }                                                                     \
        fadd2(p0, q0); fadd2(p1, q1);                                         \
        float2 f0 = unpack2f(p0), f1 = unpack2f(p1);                          \
        P[kq][o] = make_float2(f0.x + f0.y, f1.x + f1.y);                     \
    }

    // Combine + broadcast + barrier; PREFETCH between arrive/wait.
    // ALLPEERS=1: store to all 3 peers; 0: only to the tail-owner peer.
    #define EXCHANGE(OUT, BIASEXPR, PREFETCH, ALLPEERS)                       \
    {                                                                         \
        __syncthreads();                                                      \
        if (t < 128) {                                                        \
            int rr = t >> 6, oc = t & 63;                                     \
            int ro2 = (int)rank * 64 + oc;                                    \
            float v = 0.f;                                                    \
            _Pragma("unroll")                                                 \
            for (int j = 0; j < 8; j++) {                                     \
                float2 pv = P[j][oc];                                         \
                v += rr ? pv.y : pv.x;                                        \
            }                                                                 \
            float bb = (BIASEXPR);                                            \
            v = fmaxf(v + bb, 0.f);                                           \
            OUT[rr][ro2] = v;                                                 \
            U32 la = smem_u32(&OUT[rr][ro2]);                                 \
            if (ALLPEERS) {                                                   \
                _Pragma("unroll")                                             \
                for (int p = 0; p < 4; p++) if (p != (int)rank) {             \
                    U32 pa;                                                   \
                    asm("mapa.shared::cluster.u32 %0, %1, %2;"                \
                        : "=r"(pa) : "r"(la), "r"(p));                        \
                    asm volatile("st.shared::cluster.f32 [%0], %1;"           \
                                 :: "r"(pa), "f"(v) : "memory");              \
                }                                                             \
            } else {                                                          \
                if (rr != (int)rank) {                                        \
                    U32 pa;                                                   \
                    asm("mapa.shared::cluster.u32 %0, %1, %2;"                \
                        : "=r"(pa) : "r"(la), "r"(rr));                       \
                    asm volatile("st.shared::cluster.f32 [%0], %1;"           \
                                 :: "r"(pa), "f"(v) : "memory");              \
                }                                                             \
            }                                                                 \
        }                                                                     \
        CLUSTER_ARRIVE();                                                     \
        PREFETCH();                                                           \
        CLUSTER_WAIT();                                                       \
    }

    auto pf_g1 = [&] { loadw<8>(wr, gat_W + 65536 + ro * 256 + kq * 32); };
    auto pf_g2 = [&] { loadw<8>(wr, gat_W + 131072 + ro * 256 + kq * 32); };
    auto pf_f  = [&] { loadw<10>(wr, W_fuse + ro * 320 + kq * 40); };
    auto pf_s1 = [&] {
        const float* p = (ro < 128) ? (W_p1 + ro * 256) : (W_d1 + (ro - 128) * 256);
        loadw<8>(wr, p + kq * 32);
    };
    auto pf_t  = [&] {
        const float* p = (o2 < 64) ? (W_p2 + o2 * 128) : (W_d2 + (o2 - 64) * 128);
        loadw<8>(wr, p + kq2 * 32);
    };

    // L1..L3: collapsed GAT [256x256]
    COMPUTE(8, A);
    EXCHANGE(B, gat_b[ro2], pf_g1, 1);
    COMPUTE(8, B);
    EXCHANGE(A, gat_b[256 + ro2], pf_g2, 1);
    COMPUTE(8, A);
    EXCHANGE(B, gat_b[512 + ro2], pf_f, 1);
    // L4: fuse [256x320] over [g3 ; emb] (emb pre-staged in B[r][256..319])
    COMPUTE(10, B);
    EXCHANGE(A, b_fuse[ro2], pf_s1, 1);
    // L5: heads stage1 [p1 ; d1] = [256x256]; only tail owners need results.
    COMPUTE(8, A);
    EXCHANGE(B, (ro2 < 128) ? b_p1[ro2] : b_d1[ro2 - 128], pf_t, 0);
    #undef COMPUTE
    #undef EXCHANGE

    // ---- Tail (CTA-local): ranks 0,1 own rows row0+rank. ----
    if ((int)rank < 2) {
        const float* Brow = B[rank];
        float* Ps = (float*)P;                       // scratch [4][128]
        // L6: [p2;d2] 128 outs, K=128 (weights already prefetched in wr)
        {
            const longlong2* Aq = (const longlong2*)Brow +
                ((o2 >= 64) ? 32 : 0) + kq2 * 8;
            ULL p0 = 0ull, q0 = 0ull;
            #pragma unroll
            for (int i = 0; i < 8; i++) {
                longlong2 x0 = Aq[i];
                ffma2(p0, (ULL)wr[i].x, (ULL)x0.x);
                ffma2(q0, (ULL)wr[i].y, (ULL)x0.y);
            }
            fadd2(p0, q0);
            float2 f0 = unpack2f(p0);
            Ps[kq2 * 128 + o2] = f0.x + f0.y;
        }
        __syncthreads();
        if (t < 128) {
            float b2 = (t < 64) ? b_p2[t] : b_d2[t - 64];
            C[t] = fmaxf(Ps[t] + Ps[128 + t] + Ps[256 + t] + Ps[384 + t] + b2, 0.f);
        }
        __syncthreads();
        // L7: price (warp 0) / direction (warp 1)
        const int w = t >> 5, lane = t & 31;
        if (w < 2) {
            const float* W3 = w ? W_d3 : W_p3;
            const float* Cv = C + w * 64;
            float v = W3[lane] * Cv[lane] + W3[lane + 32] * Cv[lane + 32];
            #pragma unroll
            for (int m = 16; m; m >>= 1)
                v += __shfl_xor_sync(0xffffffffu, v, m);
            if (lane == 0) {
                int rg = row0 + (int)rank;
                if (!w) out[rg] = v + b_p3[0];
                else    out[64 + rg] = 1.f / (1.f + __expf(-(v + b_d3[0])));
            }
        }
    }
}

extern "C" void kernel_launch(void* const* d_in, const int* in_sizes, int n_in,
                              void* d_out, int out_size) {
    const float* x      = (const float*)d_in[0];
    const int*   cidx   = (const int*)  d_in[1];
    // d_in[2] edge_index, d_in[3] edge_attr: unused (softmax collapse)
    const float* W_in   = (const float*)d_in[4];
    const float* b_in   = (const float*)d_in[5];
    const float* gat_W  = (const float*)d_in[6];
    // d_in[7..10]: attention params — unused (collapse)
    const float* gat_b  = (const float*)d_in[11];
    const float* emb    = (const float*)d_in[12];
    const float* W_fuse = (const float*)d_in[13];
    const float* b_fuse = (const float*)d_in[14];
    const float* W_p1   = (const float*)d_in[15];
    const float* b_p1   = (const float*)d_in[16];
    const float* W_p2   = (const float*)d_in[17];
    const float* b_p2   = (const float*)d_in[18];
    const float* W_p3   = (const float*)d_in[19];
    const float* b_p3   = (const float*)d_in[20];
    const float* W_d1   = (const float*)d_in[21];
    const float* b_d1   = (const float*)d_in[22];
    const float* W_d2   = (const float*)d_in[23];
    const float* b_d2   = (const float*)d_in[24];
    const float* W_d3   = (const float*)d_in[25];
    const float* b_d3   = (const float*)d_in[26];

    net_kernel<<<128, 512>>>(x, cidx, W_in, b_in, gat_W, gat_b, emb,
                             W_fuse, b_fuse, W_p1, b_p1, W_p2, b_p2,
                             W_p3, b_p3, W_d1, b_d1, W_d2, b_d2,
                             W_d3, b_d3, (float*)d_out);
}

// round 14
// speedup vs baseline: 1.4314x; 1.4314x over previous
#include <cuda_runtime.h>

// ---------------------------------------------------------------------------
// GAT collapses (uniform per-item node features; per-dst softmax weights sum
// to 1 via self-loops) => whole model = 7-layer MLP on 64 batch rows.
// SINGLE kernel: 32 clusters x 4 CTAs x 512 thr (128 CTAs = full chip).
// Cluster owns 2 rows; each CTA computes 64/256 outputs per big layer.
// Thread = (o = t>>3, ks = t&7): lane group reads 16B-interleaved quads of a
// RAW row-major weight row -> fully coalesced LDG.128 (4 lines/instr), no
// pack kernel. K-reduction intra-warp via shfl (no smem combine, no
// syncthreads); results broadcast via st.shared::cluster; barrier.cluster
// per layer with next layer's weight LDGs issued between arrive and wait.
// ---------------------------------------------------------------------------

typedef unsigned long long ULL;
typedef unsigned int U32;

__device__ __forceinline__ void ffma2(ULL& d, ULL a, ULL b) {
    asm("fma.rn.f32x2 %0, %1, %2, %0;" : "+l"(d) : "l"(a), "l"(b));
}
__device__ __forceinline__ void fadd2(ULL& d, ULL a) {
    asm("add.rn.f32x2 %0, %1, %0;" : "+l"(d) : "l"(a));
}
__device__ __forceinline__ float2 unpack2f(ULL v) {
    float2 f; asm("mov.b64 {%0, %1}, %2;" : "=f"(f.x), "=f"(f.y) : "l"(v)); return f;
}
__device__ __forceinline__ U32 smem_u32(const void* p) {
    return (U32)__cvta_generic_to_shared(p);
}
#define CLUSTER_ARRIVE() asm volatile("barrier.cluster.arrive.aligned;" ::: "memory")
#define CLUSTER_WAIT()   asm volatile("barrier.cluster.wait.aligned;"   ::: "memory")

__global__ __launch_bounds__(512, 1) __cluster_dims__(4, 1, 1)
void net_kernel(
    const float* __restrict__ x, const int* __restrict__ cidx,
    const float* __restrict__ W_in, const float* __restrict__ b_in,
    const float* __restrict__ gat_W, const float* __restrict__ gat_b,
    const float* __restrict__ emb,
    const float* __restrict__ W_fuse, const float* __restrict__ b_fuse,
    const float* __restrict__ W_p1, const float* __restrict__ b_p1,
    const float* __restrict__ W_p2, const float* __restrict__ b_p2,
    const float* __restrict__ W_p3, const float* __restrict__ b_p3,
    const float* __restrict__ W_d1, const float* __restrict__ b_d1,
    const float* __restrict__ W_d2, const float* __restrict__ b_d2,
    const float* __restrict__ W_d3, const float* __restrict__ b_d3,
    float* __restrict__ out) {

    __shared__ __align__(16) float X[2][64];
    __shared__ __align__(16) float A[2][336];
    __shared__ __align__(16) float B[2][336];
    __shared__ __align__(16) float C[128];

    const int t   = threadIdx.x;
    const int o   = t >> 3;      // big layers: output in CTA's 64-slice
    const int ks  = t & 7;       // big layers: K eighth (lane bits 0..2)
    const int o0  = t >> 1;      // L0: output 0..255
    const int kh  = t & 1;       // L0: K half
    const int o3  = t >> 2;      // tail: output 0..127
    const int ks3 = t & 3;       // tail: K quarter
    U32 rank; asm("mov.u32 %0, %%cluster_ctarank;" : "=r"(rank));
    const int row0 = (blockIdx.x >> 2) * 2;      // cluster's first global row
    const int ro   = (int)rank * 64 + o;         // big-layer weight row

    longlong2 wr[10];

    // ---- prefetch L0 weights (quads kh + 2i of raw row o0) ----
    {
        const longlong2* Wq = (const longlong2*)(W_in + o0 * 64);
        #pragma unroll
        for (int i = 0; i < 8; i++) wr[i] = Wq[kh + 2 * i];
    }

    // ---- stage inputs ----
    if (t < 32) {
        int r = t >> 4, q = t & 15;
        ((float4*)X[r])[q] = ((const float4*)x)[(row0 + r) * 16 + q];
    } else if (t < 64) {
        int i = t - 32, r = i >> 4, q = i & 15;
        int ci = cidx[row0 + r];
        ((float4*)(B[r] + 256))[q] = ((const float4*)emb)[ci * 16 + q];
    }
    __syncthreads();

    // ===== L0 (CTA-local, all 256 outputs, K=64): X -> A =====
    {
        const longlong2* a0 = (const longlong2*)X[0];
        const longlong2* a1 = (const longlong2*)X[1];
        ULL p0 = 0ull, q0 = 0ull, p1 = 0ull, q1 = 0ull;
        #pragma unroll
        for (int i = 0; i < 8; i++) {
            longlong2 x0 = a0[kh + 2 * i], x1 = a1[kh + 2 * i];
            ffma2(p0, (ULL)wr[i].x, (ULL)x0.x);
            ffma2(q0, (ULL)wr[i].y, (ULL)x0.y);
            ffma2(p1, (ULL)wr[i].x, (ULL)x1.x);
            ffma2(q1, (ULL)wr[i].y, (ULL)x1.y);
        }
        fadd2(p0, q0); fadd2(p1, q1);
        float2 f0 = unpack2f(p0), f1 = unpack2f(p1);
        float v0 = f0.x + f0.y, v1 = f1.x + f1.y;
        v0 += __shfl_xor_sync(0xffffffffu, v0, 1);
        v1 += __shfl_xor_sync(0xffffffffu, v1, 1);
        float bb = b_in[o0];
        if (kh == 0) A[0][o0] = fmaxf(v0 + bb, 0.f);
        else         A[1][o0] = fmaxf(v1 + bb, 0.f);
        // Prefetch L1 weights (big-layer mapping) before the sync.
        const longlong2* Wq = (const longlong2*)(gat_W + ro * 256);
        #pragma unroll
        for (int i = 0; i < 8; i++) wr[i] = Wq[ks + 8 * i];
        __syncthreads();
    }

    // One big-layer step: compute over quads ks+8i, intra-warp shfl reduce,
    // lanes ks=0/1 publish rows 0/1 (local + remote), barrier w/ prefetch.
    // TAILONLY: store row r only to rank r (tail owners).
    #define LAYERSTEP(NQ, IN, OUT, BIASEXPR, PREFETCH, TAILONLY)              \
    {                                                                         \
        const longlong2* a0 = (const longlong2*)IN[0] + ks;                   \
        const longlong2* a1 = (const longlong2*)IN[1] + ks;                   \
        ULL p0 = 0ull, q0 = 0ull, p1 = 0ull, q1 = 0ull;                       \
        _Pragma("unroll")                                                     \
        for (int i = 0; i < (NQ); i++) {                                      \
            longlong2 x0 = a0[8 * i], x1 = a1[8 * i];                         \
            ffma2(p0, (ULL)wr[i].x, (ULL)x0.x);                               \
            ffma2(q0, (ULL)wr[i].y, (ULL)x0.y);                               \
            ffma2(p1, (ULL)wr[i].x, (ULL)x1.x);                               \
            ffma2(q1, (ULL)wr[i].y, (ULL)x1.y);                               \
        }                                                                     \
        fadd2(p0, q0); fadd2(p1, q1);                                         \
        float2 f0 = unpack2f(p0), f1 = unpack2f(p1);                          \
        float v0 = f0.x + f0.y, v1 = f1.x + f1.y;                             \
        v0 += __shfl_xor_sync(0xffffffffu, v0, 1);                            \
        v1 += __shfl_xor_sync(0xffffffffu, v1, 1);                            \
        v0 += __shfl_xor_sync(0xffffffffu, v0, 2);                            \
        v1 += __shfl_xor_sync(0xffffffffu, v1, 2);                            \
        v0 += __shfl_xor_sync(0xffffffffu, v0, 4);                            \
        v1 += __shfl_xor_sync(0xffffffffu, v1, 4);                            \
        if (ks < 2) {                                                         \
            float bb = (BIASEXPR);                                            \
            float v = fmaxf((ks ? v1 : v0) + bb, 0.f);                        \
            if (!(TAILONLY)) {                                                \
                OUT[ks][ro] = v;                                              \
                U32 la = smem_u32(&OUT[ks][ro]);                              \
                _Pragma("unroll")                                             \
                for (int p = 0; p < 4; p++) if (p != (int)rank) {             \
                    U32 pa;                                                   \
                    asm("mapa.shared::cluster.u32 %0, %1, %2;"                \
                        : "=r"(pa) : "r"(la), "r"(p));                        \
                    asm volatile("st.shared::cluster.f32 [%0], %1;"           \
                                 :: "r"(pa), "f"(v) : "memory");              \
                }                                                             \
            } else {                                                          \
                if ((int)rank == ks) {                                        \
                    OUT[ks][ro] = v;                                          \
                } else {                                                      \
                    U32 la = smem_u32(&OUT[ks][ro]);                          \
                    U32 pa;                                                   \
                    asm("mapa.shared::cluster.u32 %0, %1, %2;"                \
                        : "=r"(pa) : "r"(la), "r"(ks));                       \
                    asm volatile("st.shared::cluster.f32 [%0], %1;"           \
                                 :: "r"(pa), "f"(v) : "memory");              \
                }                                                             \
            }                                                                 \
        }                                                                     \
        CLUSTER_ARRIVE();                                                     \
        PREFETCH();                                                           \
        CLUSTER_WAIT();                                                       \
    }

    auto pf_g1 = [&] {
        const longlong2* Wq = (const longlong2*)(gat_W + 65536 + ro * 256);
        #pragma unroll
        for (int i = 0; i < 8; i++) wr[i] = Wq[ks + 8 * i];
    };
    auto pf_g2 = [&] {
        const longlong2* Wq = (const longlong2*)(gat_W + 131072 + ro * 256);
        #pragma unroll
        for (int i = 0; i < 8; i++) wr[i] = Wq[ks + 8 * i];
    };
    auto pf_f = [&] {
        const longlong2* Wq = (const longlong2*)(W_fuse + ro * 320);
        #pragma unroll
        for (int i = 0; i < 10; i++) wr[i] = Wq[ks + 8 * i];
    };
    auto pf_s1 = [&] {
        const float* p = (ro < 128) ? (W_p1 + ro * 256)
                                    : (W_d1 + (ro - 128) * 256);
        const longlong2* Wq = (const longlong2*)p;
        #pragma unroll
        for (int i = 0; i < 8; i++) wr[i] = Wq[ks + 8 * i];
    };
    auto pf_t = [&] {
        const float* p = (o3 < 64) ? (W_p2 + o3 * 128)
                                   : (W_d2 + (o3 - 64) * 128);
        const longlong2* Wq = (const longlong2*)p;
        #pragma unroll
        for (int i = 0; i < 8; i++) wr[i] = Wq[ks3 + 4 * i];
    };

    // L1..L3: collapsed GAT [256x256]
    LAYERSTEP(8, A, B, gat_b[ro], pf_g1, 0);
    LAYERSTEP(8, B, A, gat_b[256 + ro], pf_g2, 0);
    LAYERSTEP(8, A, B, gat_b[512 + ro], pf_f, 0);
    // L4: fuse [256x320] over [g3 ; emb] (emb pre-staged at B[r][256..319])
    LAYERSTEP(10, B, A, b_fuse[ro], pf_s1, 0);
    // L5: heads stage1 [p1 ; d1] = [256x256]; only tail owners need results.
    LAYERSTEP(8, A, B, (ro < 128) ? b_p1[ro] : b_d1[ro - 128], pf_t, 1);
    #undef LAYERSTEP

    // ---- Tail (CTA-local): ranks 0,1 own rows row0+rank. ----
    if ((int)rank < 2) {
        const float* Brow = B[rank];
        // L6: [p2;d2] 128 outs, K=128 (weights prefetched in wr, quads ks3+4i)
        {
            const longlong2* Aq =
                (const longlong2*)(Brow + ((o3 >= 64) ? 128 : 0)) + ks3;
            ULL p0 = 0ull, q0 = 0ull;
            #pragma unroll
            for (int i = 0; i < 8; i++) {
                longlong2 x0 = Aq[4 * i];
                ffma2(p0, (ULL)wr[i].x, (ULL)x0.x);
                ffma2(q0, (ULL)wr[i].y, (ULL)x0.y);
            }
            fadd2(p0, q0);
            float2 f0 = unpack2f(p0);
            float v = f0.x + f0.y;
            v += __shfl_xor_sync(0xffffffffu, v, 1);
            v += __shfl_xor_sync(0xffffffffu, v, 2);
            if (ks3 == 0) {
                float b2 = (o3 < 64) ? b_p2[o3] : b_d2[o3 - 64];
                C[o3] = fmaxf(v + b2, 0.f);
            }
        }
        __syncthreads();
        // L7: price (warp 0) / direction (warp 1)
        const int w = t >> 5, lane = t & 31;
        if (w < 2) {
            const float* W3 = w ? W_d3 : W_p3;
            const float* Cv = C + w * 64;
            float v = W3[lane] * Cv[lane] + W3[lane + 32] * Cv[lane + 32];
            #pragma unroll
            for (int m = 16; m; m >>= 1)
                v += __shfl_xor_sync(0xffffffffu, v, m);
            if (lane == 0) {
                int rg = row0 + (int)rank;
                if (!w) out[rg] = v + b_p3[0];
                else    out[64 + rg] = 1.f / (1.f + __expf(-(v + b_d3[0])));
            }
        }
    }
}

extern "C" void kernel_launch(void* const* d_in, const int* in_sizes, int n_in,
                              void* d_out, int out_size) {
    const float* x      = (const float*)d_in[0];
    const int*   cidx   = (const int*)  d_in[1];
    // d_in[2] edge_index, d_in[3] edge_attr: unused (softmax collapse)
    const float* W_in   = (const float*)d_in[4];
    const float* b_in   = (const float*)d_in[5];
    const float* gat_W  = (const float*)d_in[6];
    // d_in[7..10]: attention params — unused (collapse)
    const float* gat_b  = (const float*)d_in[11];
    const float* emb    = (const float*)d_in[12];
    const float* W_fuse = (const float*)d_in[13];
    const float* b_fuse = (const float*)d_in[14];
    const float* W_p1   = (const float*)d_in[15];
    const float* b_p1   = (const float*)d_in[16];
    const float* W_p2   = (const float*)d_in[17];
    const float* b_p2   = (const float*)d_in[18];
    const float* W_p3   = (const float*)d_in[19];
    const float* b_p3   = (const float*)d_in[20];
    const float* W_d1   = (const float*)d_in[21];
    const float* b_d1   = (const float*)d_in[22];
    const float* W_d2   = (const float*)d_in[23];
    const float* b_d2   = (const float*)d_in[24];
    const float* W_d3   = (const float*)d_in[25];
    const float* b_d3   = (const float*)d_in[26];

    net_kernel<<<128, 512>>>(x, cidx, W_in, b_in, gat_W, gat_b, emb,
                             W_fuse, b_fuse, W_p1, b_p1, W_p2, b_p2,
                             W_p3, b_p3, W_d1, b_d1, W_d2, b_d2,
                             W_d3, b_d3, (float*)d_out);
}

// round 15
// speedup vs baseline: 1.5970x; 1.1157x over previous
#include <cuda_runtime.h>

// ---------------------------------------------------------------------------
// GAT collapses (uniform per-item node features; per-dst softmax weights sum
// to 1 via self-loops) => whole model = 7-layer MLP on 64 batch rows.
// 32 clusters x 4 CTAs x 512 thr. Cluster owns 2 rows; CTA computes 64/256
// outputs per big layer; results broadcast via st.shared::cluster +
// barrier.cluster. Packed k4-interleaved weights (pack_kernel + PDL).
// R15: biases preloaded to smem (no bias LDG on critical path); next-layer
// weight prefetch issued right after the FFMA loop (hidden under combine +
// barrier, not just the wait window); mapa peer bases precomputed once.
// ---------------------------------------------------------------------------

typedef unsigned long long ULL;
typedef unsigned int U32;

__device__ __forceinline__ void ffma2(ULL& d, ULL a, ULL b) {
    asm("fma.rn.f32x2 %0, %1, %2, %0;" : "+l"(d) : "l"(a), "l"(b));
}
__device__ __forceinline__ void fadd2(ULL& d, ULL a) {
    asm("add.rn.f32x2 %0, %1, %0;" : "+l"(d) : "l"(a));
}
__device__ __forceinline__ float2 unpack2f(ULL v) {
    float2 f; asm("mov.b64 {%0, %1}, %2;" : "=f"(f.x), "=f"(f.y) : "l"(v)); return f;
}
__device__ __forceinline__ U32 smem_u32(const void* p) {
    return (U32)__cvta_generic_to_shared(p);
}
#define CLUSTER_ARRIVE() asm volatile("barrier.cluster.arrive.aligned;" ::: "memory")
#define CLUSTER_WAIT()   asm volatile("barrier.cluster.wait.aligned;"   ::: "memory")

// ---- packed weights: quad idx (in region) = k4*O + o ----------------------
#define Q_IN   0        // W_in   256x64   O=256 Kq=16
#define Q_G0   4096     // gat_W0 256x256  O=256 Kq=64
#define Q_G1   20480
#define Q_G2   36864
#define Q_F    53248    // W_fuse 256x320  O=256 Kq=80
#define Q_S1   73728    // [p1;d1] 256x256 O=256 Kq=64
#define Q_2    90112    // [p2;d2] 128x128 O=128 Kq=32
#define Q_TOTAL 94208

__device__ __align__(16) float4 g_packed[Q_TOTAL];

__global__ void pack_kernel(const float4* __restrict__ W_in,
                            const float4* __restrict__ gat_W,
                            const float4* __restrict__ W_fuse,
                            const float4* __restrict__ W_p1,
                            const float4* __restrict__ W_d1,
                            const float4* __restrict__ W_p2,
                            const float4* __restrict__ W_d2) {
    int e = blockIdx.x * blockDim.x + threadIdx.x;   // 184*512 = 94208 exactly
    if (e < Q_TOTAL) {
        const float4* src; int le, Kq, Ocomb, obase, offq;
        if (e < 4096)       { src = W_in;          le = e;         Kq = 16; Ocomb = 256; obase = 0;   offq = Q_IN; }
        else if (e < 20480) { src = gat_W;         le = e - 4096;  Kq = 64; Ocomb = 256; obase = 0;   offq = Q_G0; }
        else if (e < 36864) { src = gat_W + 16384; le = e - 20480; Kq = 64; Ocomb = 256; obase = 0;   offq = Q_G1; }
        else if (e < 53248) { src = gat_W + 32768; le = e - 36864; Kq = 64; Ocomb = 256; obase = 0;   offq = Q_G2; }
        else if (e < 73728) { src = W_fuse;        le = e - 53248; Kq = 80; Ocomb = 256; obase = 0;   offq = Q_F;  }
        else if (e < 81920) { src = W_p1;          le = e - 73728; Kq = 64; Ocomb = 256; obase = 0;   offq = Q_S1; }
        else if (e < 90112) { src = W_d1;          le = e - 81920; Kq = 64; Ocomb = 256; obase = 128; offq = Q_S1; }
        else if (e < 92160) { src = W_p2;          le = e - 90112; Kq = 32; Ocomb = 128; obase = 0;   offq = Q_2;  }
        else                { src = W_d2;          le = e - 92160; Kq = 32; Ocomb = 128; obase = 64;  offq = Q_2;  }
        int o  = le / Kq;
        int k4 = le - o * Kq;
        g_packed[offq + k4 * Ocomb + obase + o] = src[le];
    }
    asm volatile("griddepcontrol.launch_dependents;" ::: "memory");
}

template<int N, int STRIDE>
__device__ __forceinline__ void loadw(longlong2* wr, const longlong2* Wp) {
    #pragma unroll
    for (int i = 0; i < N; i++) wr[i] = Wp[(size_t)i * STRIDE];
}

// smem bias layout offsets
#define SB_IN   0      // b_in   256
#define SB_GAT  256    // gat_b  768
#define SB_F    1024   // b_fuse 256
#define SB_P1   1280   // b_p1   128
#define SB_D1   1408   // b_d1   128
#define SB_P2   1536   // b_p2    64
#define SB_D2   1600   // b_d2    64
#define SB_TOT  1664

__global__ __launch_bounds__(512, 1) __cluster_dims__(4, 1, 1)
void net_kernel(
    const float* __restrict__ x, const int* __restrict__ cidx,
    const float* __restrict__ b_in, const float* __restrict__ gat_b,
    const float* __restrict__ emb, const float* __restrict__ b_fuse,
    const float* __restrict__ b_p1, const float* __restrict__ b_d1,
    const float* __restrict__ b_p2, const float* __restrict__ b_d2,
    const float* __restrict__ W_p3, const float* __restrict__ b_p3,
    const float* __restrict__ W_d3, const float* __restrict__ b_d3,
    float* __restrict__ out) {

    __shared__ __align__(16) float  X[2][64];
    __shared__ __align__(16) float  A[2][336];
    __shared__ __align__(16) float  B[2][336];
    __shared__ __align__(16) float2 P[8][64];
    __shared__ __align__(16) float  C[128];
    __shared__ __align__(16) float  sBias[SB_TOT];

    const int t  = threadIdx.x;
    const int o  = t & 63;      // output within CTA's 64-slice (big layers)
    const int kq = t >> 6;      // K eighth 0..7
    U32 rank; asm("mov.u32 %0, %%cluster_ctarank;" : "=r"(rank));
    const int row0 = (blockIdx.x >> 2) * 2;      // cluster's first global row
    const int kq2 = t >> 7;                      // tail: K quarter 0..3
    const int o2  = t & 127;                     // tail: 0..63 p2, 64..127 d2
    const int oc0 = t & 255, kh0 = t >> 8;       // L0-local mapping

    const longlong2* GP = (const longlong2*)g_packed;
    longlong2 wr[10];

    // ---- precompute cluster peer smem bases (anchor = X) ----
    const U32 anchor = smem_u32(&X[0][0]);
    U32 pm[4];
    #pragma unroll
    for (int p = 0; p < 4; p++)
        asm("mapa.shared::cluster.u32 %0, %1, %2;" : "=r"(pm[p]) : "r"(anchor), "r"(p));

    // ---- stage inputs + ALL biases (independent of pack output) ----
    if (t < 32) {
        int r = t >> 4, q = t & 15;
        ((float4*)X[r])[q] = ((const float4*)x)[(row0 + r) * 16 + q];
    } else if (t < 64) {
        int i = t - 32, r = i >> 4, q = i & 15;
        int ci = cidx[row0 + r];
        ((float4*)(B[r] + 256))[q] = ((const float4*)emb)[ci * 16 + q];
    }
    {
        if (t < 256) sBias[SB_IN + t] = b_in[t];
        for (int i = t; i < 768; i += 512) sBias[SB_GAT + i] = gat_b[i];
        if (t < 256) sBias[SB_F + t] = b_fuse[t];
        if (t < 128) sBias[SB_P1 + t] = b_p1[t];
        else if (t < 256) sBias[SB_D1 + t - 128] = b_d1[t - 128];
        else if (t < 320) sBias[SB_P2 + t - 256] = b_p2[t - 256];
        else if (t < 384) sBias[SB_D2 + t - 320] = b_d2[t - 320];
    }

    // ---- wait for pack_kernel's writes to be visible (PDL) ----
    asm volatile("griddepcontrol.wait;" ::: "memory");
    __syncthreads();

    // ===== L0 (CTA-local, all 256 outputs, K=64): X -> A =====
    {
        float2 (*P2)[256] = (float2 (*)[256])&P[0][0];
        loadw<8, 256>(wr, GP + Q_IN + (size_t)(kh0 * 8) * 256 + oc0);
        const longlong2* a0 = (const longlong2*)X[0] + kh0 * 8;
        const longlong2* a1 = (const longlong2*)X[1] + kh0 * 8;
        ULL p0 = 0ull, q0 = 0ull, p1 = 0ull, q1 = 0ull;
        #pragma unroll
        for (int i = 0; i < 8; i++) {
            longlong2 x0 = a0[i], x1 = a1[i];
            ffma2(p0, (ULL)wr[i].x, (ULL)x0.x);
            ffma2(q0, (ULL)wr[i].y, (ULL)x0.y);
            ffma2(p1, (ULL)wr[i].x, (ULL)x1.x);
            ffma2(q1, (ULL)wr[i].y, (ULL)x1.y);
        }
        fadd2(p0, q0); fadd2(p1, q1);
        float2 f0 = unpack2f(p0), f1 = unpack2f(p1);
        P2[kh0][oc0] = make_float2(f0.x + f0.y, f1.x + f1.y);
        // Prefetch L1 weights (big-layer mapping) before the sync.
        loadw<8, 256>(wr, GP + Q_G0 + (size_t)(kq * 8) * 256 + rank * 64 + o);
        __syncthreads();
        {
            int rr = t >> 8, oc = t & 255;
            float v = rr ? (P2[0][oc].y + P2[1][oc].y)
                         : (P2[0][oc].x + P2[1][oc].x);
            A[rr][oc] = fmaxf(v + sBias[SB_IN + oc], 0.f);
        }
        __syncthreads();
    }

    // FFMA phase over this thread's K-slice; partials into P.
    #define COMPUTE(KQ4, IN)                                                  \
    {                                                                         \
        const longlong2* a0 = (const longlong2*)IN[0] + kq * (KQ4);           \
        const longlong2* a1 = (const longlong2*)IN[1] + kq * (KQ4);           \
        ULL p0 = 0ull, q0 = 0ull, p1 = 0ull, q1 = 0ull;                       \
        _Pragma("unroll")                                                     \
        for (int i = 0; i < (KQ4); i++) {                                     \
            longlong2 x0 = a0[i], x1 = a1[i];                                 \
            ffma2(p0, (ULL)wr[i].x, (ULL)x0.x);                               \
            ffma2(q0, (ULL)wr[i].y, (ULL)x0.y);                               \
            ffma2(p1, (ULL)wr[i].x, (ULL)x1.x);                               \
            ffma2(q1, (ULL)wr[i].y, (ULL)x1.y);                               \
        }                                                                     \
        fadd2(p0, q0); fadd2(p1, q1);                                         \
        float2 f0 = unpack2f(p0), f1 = unpack2f(p1);                          \
        P[kq][o] = make_float2(f0.x + f0.y, f1.x + f1.y);                     \
    }

    // Combine (smem bias) + broadcast + barrier. Prefetch already issued.
    #define EXCHANGE(OUT, BIASEXPR, ALLPEERS)                                 \
    {                                                                         \
        __syncthreads();                                                      \
        if (t < 128) {                                                        \
            int rr = t >> 6, oc = t & 63;                                     \
            int ro2 = (int)rank * 64 + oc;                                    \
            float v = 0.f;                                                    \
            _Pragma("unroll")                                                 \
            for (int j = 0; j < 8; j++) {                                     \
                float2 pv = P[j][oc];                                         \
                v += rr ? pv.y : pv.x;                                        \
            }                                                                 \
            float bb = (BIASEXPR);                                            \
            v = fmaxf(v + bb, 0.f);                                           \
            OUT[rr][ro2] = v;                                                 \
            U32 delta = smem_u32(&OUT[rr][ro2]) - anchor;                     \
            if (ALLPEERS) {                                                   \
                _Pragma("unroll")                                             \
                for (int p = 0; p < 4; p++) if (p != (int)rank) {             \
                    asm volatile("st.shared::cluster.f32 [%0], %1;"           \
                                 :: "r"(pm[p] + delta), "f"(v) : "memory");   \
                }                                                             \
            } else {                                                          \
                if (rr != (int)rank) {                                        \
                    asm volatile("st.shared::cluster.f32 [%0], %1;"           \
                                 :: "r"(pm[rr] + delta), "f"(v) : "memory");  \
                }                                                             \
            }                                                                 \
        }                                                                     \
        CLUSTER_ARRIVE();                                                     \
        CLUSTER_WAIT();                                                       \
    }

    auto pf_g1 = [&] { loadw<8, 256>(wr, GP + Q_G1 + (size_t)(kq * 8) * 256 + rank * 64 + o); };
    auto pf_g2 = [&] { loadw<8, 256>(wr, GP + Q_G2 + (size_t)(kq * 8) * 256 + rank * 64 + o); };
    auto pf_f  = [&] { loadw<10, 256>(wr, GP + Q_F + (size_t)(kq * 10) * 256 + rank * 64 + o); };
    auto pf_s1 = [&] { loadw<8, 256>(wr, GP + Q_S1 + (size_t)(kq * 8) * 256 + rank * 64 + o); };
    auto pf_t  = [&] { loadw<8, 128>(wr, GP + Q_2 + (size_t)(kq2 * 8) * 128 + o2); };

    // L1..L3: collapsed GAT [256x256]. Prefetch issued right after FFMAs.
    COMPUTE(8, A);  pf_g1();
    EXCHANGE(B, sBias[SB_GAT + ro2], 1);
    COMPUTE(8, B);  pf_g2();
    EXCHANGE(A, sBias[SB_GAT + 256 + ro2], 1);
    COMPUTE(8, A);  pf_f();
    EXCHANGE(B, sBias[SB_GAT + 512 + ro2], 1);
    // L4: fuse [256x320] over [g3 ; emb] (emb pre-staged in B[r][256..319])
    COMPUTE(10, B); pf_s1();
    EXCHANGE(A, sBias[SB_F + ro2], 1);
    // L5: heads stage1 [p1 ; d1]; only tail owners need results.
    COMPUTE(8, A);  pf_t();
    EXCHANGE(B, (ro2 < 128) ? sBias[SB_P1 + ro2] : sBias[SB_D1 + ro2 - 128], 0);
    #undef COMPUTE
    #undef EXCHANGE

    // ---- Tail (CTA-local): ranks 0,1 own rows row0+rank. ----
    if ((int)rank < 2) {
        const float* Brow = B[rank];
        float* Ps = (float*)P;                       // scratch [4][128]
        // L6: [p2;d2] 128 outs, K=128 (weights already prefetched in wr)
        {
            const longlong2* Aq = (const longlong2*)Brow +
                ((o2 >= 64) ? 32 : 0) + kq2 * 8;
            ULL p0 = 0ull, q0 = 0ull;
            #pragma unroll
            for (int i = 0; i < 8; i++) {
                longlong2 x0 = Aq[i];
                ffma2(p0, (ULL)wr[i].x, (ULL)x0.x);
                ffma2(q0, (ULL)wr[i].y, (ULL)x0.y);
            }
            fadd2(p0, q0);
            float2 f0 = unpack2f(p0);
            Ps[kq2 * 128 + o2] = f0.x + f0.y;
        }
        __syncthreads();
        if (t < 128) {
            float b2 = (t < 64) ? sBias[SB_P2 + t] : sBias[SB_D2 + t - 64];
            C[t] = fmaxf(Ps[t] + Ps[128 + t] + Ps[256 + t] + Ps[384 + t] + b2, 0.f);
        }
        __syncthreads();
        // L7: price (warp 0) / direction (warp 1)
        const int w = t >> 5, lane = t & 31;
        if (w < 2) {
            const float* W3 = w ? W_d3 : W_p3;
            const float* Cv = C + w * 64;
            float v = W3[lane] * Cv[lane] + W3[lane + 32] * Cv[lane + 32];
            #pragma unroll
            for (int m = 16; m; m >>= 1)
                v += __shfl_xor_sync(0xffffffffu, v, m);
            if (lane == 0) {
                int rg = row0 + (int)rank;
                if (!w) out[rg] = v + b_p3[0];
                else    out[64 + rg] = 1.f / (1.f + __expf(-(v + b_d3[0])));
            }
        }
    }
}

extern "C" void kernel_launch(void* const* d_in, const int* in_sizes, int n_in,
                              void* d_out, int out_size) {
    const float* x      = (const float*)d_in[0];
    const int*   cidx   = (const int*)  d_in[1];
    // d_in[2] edge_index, d_in[3] edge_attr: unused (softmax collapse)
    const float* W_in   = (const float*)d_in[4];
    const float* b_in   = (const float*)d_in[5];
    const float* gat_W  = (const float*)d_in[6];
    // d_in[7..10]: attention params — unused (collapse)
    const float* gat_b  = (const float*)d_in[11];
    const float* emb    = (const float*)d_in[12];
    const float* W_fuse = (const float*)d_in[13];
    const float* b_fuse = (const float*)d_in[14];
    const float* W_p1   = (const float*)d_in[15];
    const float* b_p1   = (const float*)d_in[16];
    const float* W_p2   = (const float*)d_in[17];
    const float* b_p2   = (const float*)d_in[18];
    const float* W_p3   = (const float*)d_in[19];
    const float* b_p3   = (const float*)d_in[20];
    const float* W_d1   = (const float*)d_in[21];
    const float* b_d1   = (const float*)d_in[22];
    const float* W_d2   = (const float*)d_in[23];
    const float* b_d2   = (const float*)d_in[24];
    const float* W_d3   = (const float*)d_in[25];
    const float* b_d3   = (const float*)d_in[26];

    pack_kernel<<<184, 512>>>((const float4*)W_in, (const float4*)gat_W,
                              (const float4*)W_fuse, (const float4*)W_p1,
                              (const float4*)W_d1, (const float4*)W_p2,
                              (const float4*)W_d2);

    cudaLaunchConfig_t cfg = {};
    cfg.gridDim  = dim3(128, 1, 1);
    cfg.blockDim = dim3(512, 1, 1);
    cudaLaunchAttribute attrs[1];
    attrs[0].id = cudaLaunchAttributeProgrammaticStreamSerialization;
    attrs[0].val.programmaticStreamSerializationAllowed = 1;
    cfg.attrs = attrs;
    cfg.numAttrs = 1;
    cudaLaunchKernelEx(&cfg, net_kernel, x, cidx, b_in, gat_b, emb, b_fuse,
                       b_p1, b_d1, b_p2, b_d2, W_p3, b_p3, W_d3, b_d3,
                       (float*)d_out);
}